// round 12
// baseline (speedup 1.0000x reference)
#include <cuda_runtime.h>
#include <math.h>
#include <stdint.h>

#define C_    384
#define HH    56
#define WW    56
#define HWSZ  3136
#define NB    16
#define EPSV  1e-5f

// Scratch for x_pw: 16*384*3136 floats = 77 MB
__device__ float g_xpw[(size_t)NB * C_ * HWSZ];

__device__ __forceinline__ uint32_t cvt_tf32(float f) {
    uint32_t r;
    asm("cvt.rna.tf32.f32 %0, %1;" : "=r"(r) : "f"(f));
    return r;
}

#define MMA_TF32(c, a, b) \
    asm volatile("mma.sync.aligned.m16n8k8.row.col.f32.tf32.tf32.f32 " \
        "{%0,%1,%2,%3}, {%4,%5,%6,%7}, {%8,%9}, {%0,%1,%2,%3};" \
        : "+f"((c)[0]), "+f"((c)[1]), "+f"((c)[2]), "+f"((c)[3]) \
        : "r"((a)[0]), "r"((a)[1]), "r"((a)[2]), "r"((a)[3]), \
          "r"((b)[0]), "r"((b)[1]))

// ---------------------------------------------------------------------------
// Kernel 1 (unchanged, proven): x_pw = bn(W @ x) + x, tf32 mma.sync.
// ---------------------------------------------------------------------------
__global__ void __launch_bounds__(256) gemm_pw_kernel(
    const float* __restrict__ x,  const float* __restrict__ w,
    const float* __restrict__ gg, const float* __restrict__ bb,
    const float* __restrict__ mm, const float* __restrict__ vv)
{
    __shared__ uint32_t sA[2][16][136];
    __shared__ uint32_t sB[2][16][120];

    const int tid = threadIdx.x;
    const int wid = tid >> 5;
    const int lane = tid & 31;
    const int g   = lane >> 2;
    const int tig = lane & 3;
    const int wm  = (wid & 3) * 32;
    const int wn  = (wid >> 2) * 56;

    const int bi = blockIdx.z;
    const int m0 = blockIdx.y * 128;
    const int p0 = blockIdx.x * 112;

    const float* xb = x + (size_t)bi * C_ * HWSZ;

    float acc[2][7][4];
#pragma unroll
    for (int mt = 0; mt < 2; mt++)
#pragma unroll
        for (int nt = 0; nt < 7; nt++)
#pragma unroll
            for (int q = 0; q < 4; q++) acc[mt][nt][q] = 0.f;

    const int aq0 = tid, aq1 = tid + 256;
    const int am0 = aq0 >> 2, akq0 = aq0 & 3;
    const int am1 = aq1 >> 2, akq1 = aq1 & 3;
    const float* wp0 = w + (size_t)(m0 + am0) * C_ + akq0 * 4;
    const float* wp1 = w + (size_t)(m0 + am1) * C_ + akq1 * 4;
    const int bq0 = tid, bq1 = tid + 256;
    const int bkr0 = bq0 / 28, bnq0 = bq0 - bkr0 * 28;
    const int bkr1 = bq1 / 28, bnq1 = bq1 - bkr1 * 28;
    const bool bv1 = bq1 < 448;
    const float* xp0 = xb + (size_t)bkr0 * HWSZ + p0 + bnq0 * 4;
    const float* xp1 = bv1 ? (xb + (size_t)bkr1 * HWSZ + p0 + bnq1 * 4) : xp0;

    {
        float4 a0 = *(const float4*)(wp0);
        float4 a1 = *(const float4*)(wp1);
        sA[0][akq0 * 4 + 0][am0] = cvt_tf32(a0.x);
        sA[0][akq0 * 4 + 1][am0] = cvt_tf32(a0.y);
        sA[0][akq0 * 4 + 2][am0] = cvt_tf32(a0.z);
        sA[0][akq0 * 4 + 3][am0] = cvt_tf32(a0.w);
        sA[0][akq1 * 4 + 0][am1] = cvt_tf32(a1.x);
        sA[0][akq1 * 4 + 1][am1] = cvt_tf32(a1.y);
        sA[0][akq1 * 4 + 2][am1] = cvt_tf32(a1.z);
        sA[0][akq1 * 4 + 3][am1] = cvt_tf32(a1.w);
        float4 b0 = *(const float4*)(xp0);
        uint4 t0 = {cvt_tf32(b0.x), cvt_tf32(b0.y), cvt_tf32(b0.z), cvt_tf32(b0.w)};
        *(uint4*)(&sB[0][bkr0][bnq0 * 4]) = t0;
        if (bv1) {
            float4 b1 = *(const float4*)(xp1);
            uint4 t1 = {cvt_tf32(b1.x), cvt_tf32(b1.y), cvt_tf32(b1.z), cvt_tf32(b1.w)};
            *(uint4*)(&sB[0][bkr1][bnq1 * 4]) = t1;
        }
    }
    __syncthreads();

    for (int kc = 0; kc < 24; kc++) {
        const int buf = kc & 1;
        const bool more = kc < 23;
        float4 pa0, pa1, pb0, pb1;
        if (more) {
            const int kn = (kc + 1) * 16;
            pa0 = *(const float4*)(wp0 + kn);
            pa1 = *(const float4*)(wp1 + kn);
            pb0 = *(const float4*)(xp0 + (size_t)kn * HWSZ);
            if (bv1) pb1 = *(const float4*)(xp1 + (size_t)kn * HWSZ);
        }

#pragma unroll
        for (int kk = 0; kk < 2; kk++) {
            const int kr = kk * 8 + tig;
            const uint32_t* A0 = &sA[buf][kr][wm];
            const uint32_t* A4 = &sA[buf][kr + 4][wm];
            const uint32_t* B0 = &sB[buf][kr][wn];
            const uint32_t* B4 = &sB[buf][kr + 4][wn];
            uint32_t a[2][4], b[7][2];
#pragma unroll
            for (int mt = 0; mt < 2; mt++) {
                a[mt][0] = A0[mt * 16 + g];
                a[mt][1] = A0[mt * 16 + g + 8];
                a[mt][2] = A4[mt * 16 + g];
                a[mt][3] = A4[mt * 16 + g + 8];
            }
#pragma unroll
            for (int nt = 0; nt < 7; nt++) {
                b[nt][0] = B0[nt * 8 + g];
                b[nt][1] = B4[nt * 8 + g];
            }
#pragma unroll
            for (int mt = 0; mt < 2; mt++)
#pragma unroll
                for (int nt = 0; nt < 7; nt++)
                    MMA_TF32(acc[mt][nt], a[mt], b[nt]);
        }

        if (more) {
            const int nb = buf ^ 1;
            sA[nb][akq0 * 4 + 0][am0] = cvt_tf32(pa0.x);
            sA[nb][akq0 * 4 + 1][am0] = cvt_tf32(pa0.y);
            sA[nb][akq0 * 4 + 2][am0] = cvt_tf32(pa0.z);
            sA[nb][akq0 * 4 + 3][am0] = cvt_tf32(pa0.w);
            sA[nb][akq1 * 4 + 0][am1] = cvt_tf32(pa1.x);
            sA[nb][akq1 * 4 + 1][am1] = cvt_tf32(pa1.y);
            sA[nb][akq1 * 4 + 2][am1] = cvt_tf32(pa1.z);
            sA[nb][akq1 * 4 + 3][am1] = cvt_tf32(pa1.w);
            uint4 t0 = {cvt_tf32(pb0.x), cvt_tf32(pb0.y), cvt_tf32(pb0.z), cvt_tf32(pb0.w)};
            *(uint4*)(&sB[nb][bkr0][bnq0 * 4]) = t0;
            if (bv1) {
                uint4 t1 = {cvt_tf32(pb1.x), cvt_tf32(pb1.y), cvt_tf32(pb1.z), cvt_tf32(pb1.w)};
                *(uint4*)(&sB[nb][bkr1][bnq1 * 4]) = t1;
            }
        }
        __syncthreads();
    }

    float sc[2][2], sh[2][2];
#pragma unroll
    for (int mt = 0; mt < 2; mt++)
#pragma unroll
        for (int h = 0; h < 2; h++) {
            const int o = m0 + wm + mt * 16 + h * 8 + g;
            const float s = gg[o] * rsqrtf(vv[o] + EPSV);
            sc[mt][h] = s;
            sh[mt][h] = fmaf(-mm[o], s, bb[o]);
        }

#pragma unroll
    for (int mt = 0; mt < 2; mt++)
#pragma unroll
        for (int h = 0; h < 2; h++) {
            const int o = m0 + wm + mt * 16 + h * 8 + g;
            const size_t rb = ((size_t)bi * C_ + o) * HWSZ + p0 + wn + 2 * tig;
#pragma unroll
            for (int nt = 0; nt < 7; nt++) {
                const size_t idx = rb + nt * 8;
                float2 xr = *(const float2*)(x + idx);
                const float c0 = acc[mt][nt][h * 2 + 0];
                const float c1 = acc[mt][nt][h * 2 + 1];
                float2 ov;
                ov.x = fmaf(c0, sc[mt][h], sh[mt][h]) + xr.x;
                ov.y = fmaf(c1, sc[mt][h], sh[mt][h]) + xr.y;
                *(float2*)(g_xpw + idx) = ov;
            }
        }
}

// ---------------------------------------------------------------------------
// Kernel 2 v9 (TENSOR-CORE dwconv): out = gelu(bn(dwconv13(x_pw)) + bn(x_pw*dw1_w))
// Row-Toeplitz: per input row ri, S[x, i] = sum_j w[i,j]*in[ri, x+j] via 4
// mma.m16n8k8.tf32 (N = vertical tap i padded to 16, K = horiz tap j padded
// to 16, B = transposed weights preloaded). Stage2 on CUDA cores:
// out[r,x] = sum_i S_{r+i}[x,i] -> only 13 FADDs/output (was 169 FMAs).
// S lives in a per-warp 16-slot smem ring (i-stride 20, conflict-free STS.64).
// Stage2 for row ri-13 overlaps stage1 of ri (independent).
// CTA = one (channel, batch) image, 4 warps x 16-wide x-strips.
// ---------------------------------------------------------------------------
__global__ void __launch_bounds__(128) dw_bn_gelu_kernel(
    const float* __restrict__ kw,
    const float* __restrict__ kg,  const float* __restrict__ kb,
    const float* __restrict__ km,  const float* __restrict__ kv,
    const float* __restrict__ d1w, const float* __restrict__ d1g,
    const float* __restrict__ d1b, const float* __restrict__ d1m,
    const float* __restrict__ d1v,
    float* __restrict__ out)
{
    extern __shared__ float sm[];
    // layout: [0, 5056) padded input (68 rows x stride 72 + zero pad)
    //         [5056, 25536) S rings: warp w at 5056 + w*5120 (16 slots x 320)
    float* s_in = sm;

    const int c   = blockIdx.x;
    const int bi  = blockIdx.y;
    const int tid = threadIdx.x;
    const int w   = tid >> 5;
    const int lane = tid & 31;
    const int g   = lane >> 2;    // 0..7
    const int tig = lane & 3;     // 0..3

    // ---- stage padded input (fp32, zero-filled borders and tail pad) ----
    const float* src = g_xpw + ((size_t)bi * C_ + c) * HWSZ;
    for (int idx = tid; idx < 5056; idx += 128) {
        float v = 0.f;
        if (idx < 4896) {
            const int row = idx / 72;
            const int col = idx - row * 72;
            const int gh = row - 6, gw = col - 6;
            if (gh >= 0 && gh < HH && gw >= 0 && gw < WW) v = src[gh * WW + gw];
        }
        s_in[idx] = v;
    }

    // ---- preload transposed weight fragments B[k=j][n=i], zero-padded ----
    uint32_t bf[2][2][2];
    {
        const float* wb = kw + (size_t)c * 169;
#pragma unroll
        for (int kc = 0; kc < 2; kc++)
#pragma unroll
            for (int nc = 0; nc < 2; nc++) {
                const int i = nc * 8 + g;
                const int j0 = kc * 8 + tig;
                const int j1 = j0 + 4;
                bf[kc][nc][0] = (i < 13 && j0 < 13) ? cvt_tf32(wb[i * 13 + j0]) : 0u;
                bf[kc][nc][1] = (i < 13 && j1 < 13) ? cvt_tf32(wb[i * 13 + j1]) : 0u;
            }
    }

    // ---- per-channel constants ----
    const float sk  = kg[c] * rsqrtf(kv[c] + EPSV);
    const float shk = fmaf(-km[c], sk, kb[c]);
    const float s1  = d1g[c] * rsqrtf(d1v[c] + EPSV);
    const float a2c = d1w[c] * s1;
    const float b2c = fmaf(-d1m[c], s1, d1b[c]);

    __syncthreads();

    const int x0 = w * 16;
    float* Sw = sm + 5056 + w * 5120;
    const int xl = lane & 15;
    const int xg = x0 + xl;
    float* ob = out + ((size_t)bi * C_ + c) * HWSZ;
    const float RS2 = 0.70710678118654752f;

    for (int ri = 0; ri <= 68; ri++) {
        // ---- stage 1: horizontal convs for input row ri via tensor cores ----
        if (ri < 68) {
            const float* rp = s_in + ri * 72 + x0 + g + tig;
            const float v0 = rp[0],  v1 = rp[4],  v2 = rp[8];
            const float v3 = rp[12], v4 = rp[16], v5 = rp[20];
            uint32_t a0[4] = {cvt_tf32(v0), cvt_tf32(v2), cvt_tf32(v1), cvt_tf32(v3)};
            uint32_t a1[4] = {cvt_tf32(v2), cvt_tf32(v4), cvt_tf32(v3), cvt_tf32(v5)};
            float acc0[4] = {0.f, 0.f, 0.f, 0.f};
            float acc1[4] = {0.f, 0.f, 0.f, 0.f};
            MMA_TF32(acc0, a0, bf[0][0]);
            MMA_TF32(acc0, a1, bf[1][0]);
            MMA_TF32(acc1, a0, bf[0][1]);
            MMA_TF32(acc1, a1, bf[1][1]);
            float* Ss = Sw + (ri & 15) * 320;
            *(float2*)(Ss + g * 20 + 2 * tig)           = make_float2(acc0[0], acc0[1]);
            *(float2*)(Ss + (g + 8) * 20 + 2 * tig)     = make_float2(acc0[2], acc0[3]);
            *(float2*)(Ss + g * 20 + 8 + 2 * tig)       = make_float2(acc1[0], acc1[1]);
            *(float2*)(Ss + (g + 8) * 20 + 8 + 2 * tig) = make_float2(acc1[2], acc1[3]);
        }
        __syncwarp();

        // ---- stage 2: finalize output row r = ri - 13 (uses slots ri-13..ri-1) ----
        const int r = ri - 13;
        if (r >= 0) {
            float part = 0.f;
            if (lane < 16) {
#pragma unroll
                for (int i = 0; i < 7; i++)
                    part += Sw[((r + i) & 15) * 320 + xl * 20 + i];
            } else {
#pragma unroll
                for (int i = 7; i < 13; i++)
                    part += Sw[((r + i) & 15) * 320 + xl * 20 + i];
            }
            const float tot = part + __shfl_xor_sync(0xffffffffu, part, 16);
            if (lane < 16 && xg < WW) {
                const float cv = s_in[(r + 6) * 72 + xg + 6];   // exact fp32 center
                const float v = fmaf(tot, sk, shk) + fmaf(cv, a2c, b2c);
                ob[r * WW + xg] = 0.5f * v * (1.f + erff(v * RS2));
            }
        }
    }
}

// ---------------------------------------------------------------------------
extern "C" void kernel_launch(void* const* d_in, const int* in_sizes, int n_in,
                              void* d_out, int out_size)
{
    const float* x     = (const float*)d_in[0];
    const float* pw_w  = (const float*)d_in[1];
    const float* pw_g  = (const float*)d_in[2];
    const float* pw_b  = (const float*)d_in[3];
    const float* pw_m  = (const float*)d_in[4];
    const float* pw_v  = (const float*)d_in[5];
    const float* dwk_w = (const float*)d_in[6];
    const float* dwk_g = (const float*)d_in[7];
    const float* dwk_b = (const float*)d_in[8];
    const float* dwk_m = (const float*)d_in[9];
    const float* dwk_v = (const float*)d_in[10];
    const float* dw1_w = (const float*)d_in[11];
    const float* dw1_g = (const float*)d_in[12];
    const float* dw1_b = (const float*)d_in[13];
    const float* dw1_m = (const float*)d_in[14];
    const float* dw1_v = (const float*)d_in[15];
    float* out = (float*)d_out;

    dim3 g1(HWSZ / 112, C_ / 128, NB);   // (28, 3, 16)
    gemm_pw_kernel<<<g1, 256>>>(x, pw_w, pw_g, pw_b, pw_m, pw_v);

    const int dyn_smem = 25536 * 4;      // 102,144 B
    cudaFuncSetAttribute(dw_bn_gelu_kernel,
                         cudaFuncAttributeMaxDynamicSharedMemorySize, dyn_smem);
    dim3 g2(C_, NB);                      // (384, 16), one image per block
    dw_bn_gelu_kernel<<<g2, 128, dyn_smem>>>(dwk_w, dwk_g, dwk_b, dwk_m, dwk_v,
                                             dw1_w, dw1_g, dw1_b, dw1_m, dw1_v, out);
}

// round 13
// speedup vs baseline: 1.4176x; 1.4176x over previous
#include <cuda_runtime.h>
#include <math.h>
#include <stdint.h>

#define C_    384
#define HH    56
#define WW    56
#define HWSZ  3136
#define NB    16
#define EPSV  1e-5f

#define BAND     8
#define INROWS   20      // BAND + 12 halo
#define INSTRIDE 80
#define SX       56
#define SI       14
// dynamic smem layout (words): [0,1600) tf32 input; [1600, 17280) S; [17280, 17449) weights
#define DW_SMEM_WORDS (1600 + 15680 + 169)

// Scratch for x_pw: 16*384*3136 floats = 77 MB
__device__ float g_xpw[(size_t)NB * C_ * HWSZ];

__device__ __forceinline__ uint32_t cvt_tf32(float f) {
    uint32_t r;
    asm("cvt.rna.tf32.f32 %0, %1;" : "=r"(r) : "f"(f));
    return r;
}

#define MMA_TF32(c, a, b) \
    asm volatile("mma.sync.aligned.m16n8k8.row.col.f32.tf32.tf32.f32 " \
        "{%0,%1,%2,%3}, {%4,%5,%6,%7}, {%8,%9}, {%0,%1,%2,%3};" \
        : "+f"((c)[0]), "+f"((c)[1]), "+f"((c)[2]), "+f"((c)[3]) \
        : "r"((a)[0]), "r"((a)[1]), "r"((a)[2]), "r"((a)[3]), \
          "r"((b)[0]), "r"((b)[1]))

// ---------------------------------------------------------------------------
// Kernel 1 (unchanged, proven): x_pw = bn(W @ x) + x, tf32 mma.sync.
// ---------------------------------------------------------------------------
__global__ void __launch_bounds__(256) gemm_pw_kernel(
    const float* __restrict__ x,  const float* __restrict__ w,
    const float* __restrict__ gg, const float* __restrict__ bb,
    const float* __restrict__ mm, const float* __restrict__ vv)
{
    __shared__ uint32_t sA[2][16][136];
    __shared__ uint32_t sB[2][16][120];

    const int tid = threadIdx.x;
    const int wid = tid >> 5;
    const int lane = tid & 31;
    const int g   = lane >> 2;
    const int tig = lane & 3;
    const int wm  = (wid & 3) * 32;
    const int wn  = (wid >> 2) * 56;

    const int bi = blockIdx.z;
    const int m0 = blockIdx.y * 128;
    const int p0 = blockIdx.x * 112;

    const float* xb = x + (size_t)bi * C_ * HWSZ;

    float acc[2][7][4];
#pragma unroll
    for (int mt = 0; mt < 2; mt++)
#pragma unroll
        for (int nt = 0; nt < 7; nt++)
#pragma unroll
            for (int q = 0; q < 4; q++) acc[mt][nt][q] = 0.f;

    const int aq0 = tid, aq1 = tid + 256;
    const int am0 = aq0 >> 2, akq0 = aq0 & 3;
    const int am1 = aq1 >> 2, akq1 = aq1 & 3;
    const float* wp0 = w + (size_t)(m0 + am0) * C_ + akq0 * 4;
    const float* wp1 = w + (size_t)(m0 + am1) * C_ + akq1 * 4;
    const int bq0 = tid, bq1 = tid + 256;
    const int bkr0 = bq0 / 28, bnq0 = bq0 - bkr0 * 28;
    const int bkr1 = bq1 / 28, bnq1 = bq1 - bkr1 * 28;
    const bool bv1 = bq1 < 448;
    const float* xp0 = xb + (size_t)bkr0 * HWSZ + p0 + bnq0 * 4;
    const float* xp1 = bv1 ? (xb + (size_t)bkr1 * HWSZ + p0 + bnq1 * 4) : xp0;

    {
        float4 a0 = *(const float4*)(wp0);
        float4 a1 = *(const float4*)(wp1);
        sA[0][akq0 * 4 + 0][am0] = cvt_tf32(a0.x);
        sA[0][akq0 * 4 + 1][am0] = cvt_tf32(a0.y);
        sA[0][akq0 * 4 + 2][am0] = cvt_tf32(a0.z);
        sA[0][akq0 * 4 + 3][am0] = cvt_tf32(a0.w);
        sA[0][akq1 * 4 + 0][am1] = cvt_tf32(a1.x);
        sA[0][akq1 * 4 + 1][am1] = cvt_tf32(a1.y);
        sA[0][akq1 * 4 + 2][am1] = cvt_tf32(a1.z);
        sA[0][akq1 * 4 + 3][am1] = cvt_tf32(a1.w);
        float4 b0 = *(const float4*)(xp0);
        uint4 t0 = {cvt_tf32(b0.x), cvt_tf32(b0.y), cvt_tf32(b0.z), cvt_tf32(b0.w)};
        *(uint4*)(&sB[0][bkr0][bnq0 * 4]) = t0;
        if (bv1) {
            float4 b1 = *(const float4*)(xp1);
            uint4 t1 = {cvt_tf32(b1.x), cvt_tf32(b1.y), cvt_tf32(b1.z), cvt_tf32(b1.w)};
            *(uint4*)(&sB[0][bkr1][bnq1 * 4]) = t1;
        }
    }
    __syncthreads();

    for (int kc = 0; kc < 24; kc++) {
        const int buf = kc & 1;
        const bool more = kc < 23;
        float4 pa0, pa1, pb0, pb1;
        if (more) {
            const int kn = (kc + 1) * 16;
            pa0 = *(const float4*)(wp0 + kn);
            pa1 = *(const float4*)(wp1 + kn);
            pb0 = *(const float4*)(xp0 + (size_t)kn * HWSZ);
            if (bv1) pb1 = *(const float4*)(xp1 + (size_t)kn * HWSZ);
        }

#pragma unroll
        for (int kk = 0; kk < 2; kk++) {
            const int kr = kk * 8 + tig;
            const uint32_t* A0 = &sA[buf][kr][wm];
            const uint32_t* A4 = &sA[buf][kr + 4][wm];
            const uint32_t* B0 = &sB[buf][kr][wn];
            const uint32_t* B4 = &sB[buf][kr + 4][wn];
            uint32_t a[2][4], b[7][2];
#pragma unroll
            for (int mt = 0; mt < 2; mt++) {
                a[mt][0] = A0[mt * 16 + g];
                a[mt][1] = A0[mt * 16 + g + 8];
                a[mt][2] = A4[mt * 16 + g];
                a[mt][3] = A4[mt * 16 + g + 8];
            }
#pragma unroll
            for (int nt = 0; nt < 7; nt++) {
                b[nt][0] = B0[nt * 8 + g];
                b[nt][1] = B4[nt * 8 + g];
            }
#pragma unroll
            for (int mt = 0; mt < 2; mt++)
#pragma unroll
                for (int nt = 0; nt < 7; nt++)
                    MMA_TF32(acc[mt][nt], a[mt], b[nt]);
        }

        if (more) {
            const int nb = buf ^ 1;
            sA[nb][akq0 * 4 + 0][am0] = cvt_tf32(pa0.x);
            sA[nb][akq0 * 4 + 1][am0] = cvt_tf32(pa0.y);
            sA[nb][akq0 * 4 + 2][am0] = cvt_tf32(pa0.z);
            sA[nb][akq0 * 4 + 3][am0] = cvt_tf32(pa0.w);
            sA[nb][akq1 * 4 + 0][am1] = cvt_tf32(pa1.x);
            sA[nb][akq1 * 4 + 1][am1] = cvt_tf32(pa1.y);
            sA[nb][akq1 * 4 + 2][am1] = cvt_tf32(pa1.z);
            sA[nb][akq1 * 4 + 3][am1] = cvt_tf32(pa1.w);
            uint4 t0 = {cvt_tf32(pb0.x), cvt_tf32(pb0.y), cvt_tf32(pb0.z), cvt_tf32(pb0.w)};
            *(uint4*)(&sB[nb][bkr0][bnq0 * 4]) = t0;
            if (bv1) {
                uint4 t1 = {cvt_tf32(pb1.x), cvt_tf32(pb1.y), cvt_tf32(pb1.z), cvt_tf32(pb1.w)};
                *(uint4*)(&sB[nb][bkr1][bnq1 * 4]) = t1;
            }
        }
        __syncthreads();
    }

    float sc[2][2], sh[2][2];
#pragma unroll
    for (int mt = 0; mt < 2; mt++)
#pragma unroll
        for (int h = 0; h < 2; h++) {
            const int o = m0 + wm + mt * 16 + h * 8 + g;
            const float s = gg[o] * rsqrtf(vv[o] + EPSV);
            sc[mt][h] = s;
            sh[mt][h] = fmaf(-mm[o], s, bb[o]);
        }

#pragma unroll
    for (int mt = 0; mt < 2; mt++)
#pragma unroll
        for (int h = 0; h < 2; h++) {
            const int o = m0 + wm + mt * 16 + h * 8 + g;
            const size_t rb = ((size_t)bi * C_ + o) * HWSZ + p0 + wn + 2 * tig;
#pragma unroll
            for (int nt = 0; nt < 7; nt++) {
                const size_t idx = rb + nt * 8;
                float2 xr = *(const float2*)(x + idx);
                const float c0 = acc[mt][nt][h * 2 + 0];
                const float c1 = acc[mt][nt][h * 2 + 1];
                float2 ov;
                ov.x = fmaf(c0, sc[mt][h], sh[mt][h]) + xr.x;
                ov.y = fmaf(c1, sc[mt][h], sh[mt][h]) + xr.y;
                *(float2*)(g_xpw + idx) = ov;
            }
        }
}

// ---------------------------------------------------------------------------
// Kernel 2 v10 (banded tensor-core dwconv):
//   out = gelu(bn(dwconv13(x_pw)) + bn(x_pw*dw1_w))
// CTA = (8-row band, channel, batch), 256 threads, 3 CTAs/SM (69.8KB smem).
// Stage 1: S[row][x][i] = sum_j w[i,j]*in[row, x+j] via m16n8k8.tf32 mmas;
//   80 (row,strip) groups over 8 warps, fully parallel, no intra-stage sync.
//   Input pre-converted to tf32 in smem (cvt once at staging).
// Stage 2: out[r,x] = sum_i S[r+i][x][i] -- 13 FADDs/output on CUDA cores.
// Fragment layouts identical to the round-12 run that verified (3.2e-4).
// ---------------------------------------------------------------------------
__global__ void __launch_bounds__(256) dw_bn_gelu_kernel(
    const float* __restrict__ kw,
    const float* __restrict__ kg,  const float* __restrict__ kb,
    const float* __restrict__ km,  const float* __restrict__ kv,
    const float* __restrict__ d1w, const float* __restrict__ d1g,
    const float* __restrict__ d1b, const float* __restrict__ d1m,
    const float* __restrict__ d1v,
    float* __restrict__ out)
{
    extern __shared__ uint32_t smu[];
    uint32_t* s_in = smu;                         // [1600) tf32 input, stride 80
    float*    s_S  = (float*)(smu + 1600);        // [15680) S[row][x<56][i<14]
    float*    s_w  = (float*)(smu + 1600 + 15680);// [169) weights fp32

    const int band = blockIdx.x;    // 0..6
    const int c    = blockIdx.y;
    const int bi   = blockIdx.z;
    const int tid  = threadIdx.x;
    const int w    = tid >> 5;
    const int lane = tid & 31;
    const int g    = lane >> 2;
    const int tig  = lane & 3;
    const int r0   = band * BAND;

    const float* src = g_xpw + ((size_t)bi * C_ + c) * HWSZ;

    // ---- stage input (tf32, zero-padded halo + tail) ----
    for (int idx = tid; idx < INROWS * INSTRIDE; idx += 256) {
        const int lr = idx / INSTRIDE;
        const int lc = idx - lr * INSTRIDE;
        const int gh = r0 + lr - 6, gw = lc - 6;
        float v = 0.f;
        if (gh >= 0 && gh < HH && gw >= 0 && gw < WW) v = src[gh * WW + gw];
        s_in[idx] = cvt_tf32(v);
    }
    if (tid < 169) s_w[tid] = kw[(size_t)c * 169 + tid];
    __syncthreads();

    // ---- B fragments (transposed weights, zero-padded 13->16) ----
    uint32_t bf[2][2][2];
#pragma unroll
    for (int kc = 0; kc < 2; kc++)
#pragma unroll
        for (int nc = 0; nc < 2; nc++) {
            const int i = nc * 8 + g;
            const int j0 = kc * 8 + tig, j1 = j0 + 4;
            bf[kc][nc][0] = (i < 13 && j0 < 13) ? cvt_tf32(s_w[i * 13 + j0]) : 0u;
            bf[kc][nc][1] = (i < 13 && j1 < 13) ? cvt_tf32(s_w[i * 13 + j1]) : 0u;
        }

    // ---- stage 1: 10 independent (row,strip) mma groups per warp ----
    const int strip = w & 3;
    const int x0 = (strip == 3) ? 40 : strip * 16;   // strips cover x 0..55
    const bool storeA = (strip != 3);  // strip3's low half duplicates strip2
#pragma unroll
    for (int k = 0; k < 10; k++) {
        const int lr = (w >> 2) + 2 * k;             // rows 0..19
        const uint32_t* rp = s_in + lr * INSTRIDE + x0 + g + tig;
        uint32_t a0[4] = {rp[0], rp[8],  rp[4],  rp[12]};
        uint32_t a1[4] = {rp[8], rp[16], rp[12], rp[20]};
        float acc0[4] = {0.f, 0.f, 0.f, 0.f};
        float acc1[4] = {0.f, 0.f, 0.f, 0.f};
        MMA_TF32(acc0, a0, bf[0][0]);
        MMA_TF32(acc0, a1, bf[1][0]);
        MMA_TF32(acc1, a0, bf[0][1]);
        MMA_TF32(acc1, a1, bf[1][1]);

        float* Sb = s_S + (size_t)lr * SX * SI;
        const int xA = x0 + g, xB = x0 + g + 8;
        if (storeA) {
            *(float2*)(Sb + xA * SI + 2 * tig) = make_float2(acc0[0], acc0[1]);
            if (tig < 3)
                *(float2*)(Sb + xA * SI + 8 + 2 * tig) = make_float2(acc1[0], acc1[1]);
        }
        *(float2*)(Sb + xB * SI + 2 * tig) = make_float2(acc0[2], acc0[3]);
        if (tig < 3)
            *(float2*)(Sb + xB * SI + 8 + 2 * tig) = make_float2(acc1[2], acc1[3]);
    }
    __syncthreads();

    // ---- per-channel constants ----
    const float sk  = kg[c] * rsqrtf(kv[c] + EPSV);
    const float shk = fmaf(-km[c], sk, kb[c]);
    const float s1  = d1g[c] * rsqrtf(d1v[c] + EPSV);
    const float a2c = d1w[c] * s1;
    const float b2c = fmaf(-d1m[c], s1, d1b[c]);
    const float RS2 = 0.70710678118654752f;
    float* ob = out + ((size_t)bi * C_ + c) * HWSZ;

    // ---- stage 2: vertical accumulation + fused epilogue ----
    for (int oidx = tid; oidx < BAND * 56; oidx += 256) {
        const int r = oidx / 56;
        const int x = oidx - r * 56;
        float acc = 0.f;
#pragma unroll
        for (int i = 0; i < 13; i++)
            acc += s_S[((r + i) * SX + x) * SI + i];
        const float cv = src[(r0 + r) * WW + x];     // exact fp32 center
        const float v = fmaf(acc, sk, shk) + fmaf(cv, a2c, b2c);
        ob[(r0 + r) * WW + x] = 0.5f * v * (1.f + erff(v * RS2));
    }
}

// ---------------------------------------------------------------------------
extern "C" void kernel_launch(void* const* d_in, const int* in_sizes, int n_in,
                              void* d_out, int out_size)
{
    const float* x     = (const float*)d_in[0];
    const float* pw_w  = (const float*)d_in[1];
    const float* pw_g  = (const float*)d_in[2];
    const float* pw_b  = (const float*)d_in[3];
    const float* pw_m  = (const float*)d_in[4];
    const float* pw_v  = (const float*)d_in[5];
    const float* dwk_w = (const float*)d_in[6];
    const float* dwk_g = (const float*)d_in[7];
    const float* dwk_b = (const float*)d_in[8];
    const float* dwk_m = (const float*)d_in[9];
    const float* dwk_v = (const float*)d_in[10];
    const float* dw1_w = (const float*)d_in[11];
    const float* dw1_g = (const float*)d_in[12];
    const float* dw1_b = (const float*)d_in[13];
    const float* dw1_m = (const float*)d_in[14];
    const float* dw1_v = (const float*)d_in[15];
    float* out = (float*)d_out;

    dim3 g1(HWSZ / 112, C_ / 128, NB);   // (28, 3, 16)
    gemm_pw_kernel<<<g1, 256>>>(x, pw_w, pw_g, pw_b, pw_m, pw_v);

    const int dyn_smem = DW_SMEM_WORDS * 4;   // 69,796 B
    cudaFuncSetAttribute(dw_bn_gelu_kernel,
                         cudaFuncAttributeMaxDynamicSharedMemorySize, dyn_smem);
    dim3 g2(7, C_, NB);                       // (7 bands, 384, 16)
    dw_bn_gelu_kernel<<<g2, 256, dyn_smem>>>(dwk_w, dwk_g, dwk_b, dwk_m, dwk_v,
                                             dw1_w, dw1_g, dw1_b, dw1_m, dw1_v, out);
}

// round 14
// speedup vs baseline: 2.3046x; 1.6257x over previous
#include <cuda_runtime.h>
#include <math.h>
#include <stdint.h>

#define C_    384
#define HH    56
#define WW    56
#define HWSZ  3136
#define NB    16
#define EPSV  1e-5f

// Device scratch: x_pw (fp32), X in tf32, W in tf32
__device__ float    g_xpw[(size_t)NB * C_ * HWSZ];
__device__ uint32_t g_xtf[(size_t)NB * C_ * HWSZ];
__device__ uint32_t g_wtf[(size_t)C_ * C_];

__device__ __forceinline__ uint32_t cvt_tf32(float f) {
    uint32_t r;
    asm("cvt.rna.tf32.f32 %0, %1;" : "=r"(r) : "f"(f));
    return r;
}

#define MMA_TF32(c, a, b) \
    asm volatile("mma.sync.aligned.m16n8k8.row.col.f32.tf32.tf32.f32 " \
        "{%0,%1,%2,%3}, {%4,%5,%6,%7}, {%8,%9}, {%0,%1,%2,%3};" \
        : "+f"((c)[0]), "+f"((c)[1]), "+f"((c)[2]), "+f"((c)[3]) \
        : "r"((a)[0]), "r"((a)[1]), "r"((a)[2]), "r"((a)[3]), \
          "r"((b)[0]), "r"((b)[1]))

#define CP_ASYNC16(dst, src) \
    asm volatile("cp.async.ca.shared.global [%0], [%1], 16;" :: "r"(dst), "l"(src))
#define CP_COMMIT() asm volatile("cp.async.commit_group;" ::: "memory")
#define CP_WAIT1()  asm volatile("cp.async.wait_group 1;" ::: "memory")

__device__ __forceinline__ uint32_t smem_u32(const void* p) {
    uint32_t a;
    asm("{ .reg .u64 t; cvta.to.shared.u64 t, %1; cvt.u32.u64 %0, t; }" : "=r"(a) : "l"(p));
    return a;
}

// ---------------------------------------------------------------------------
// Pre-convert kernels: fp32 -> tf32(rna) bit patterns
// ---------------------------------------------------------------------------
__global__ void cvt_x_kernel(const float* __restrict__ x) {
    const size_t i = ((size_t)blockIdx.x * 256 + threadIdx.x) * 4;
    float4 v = *(const float4*)(x + i);
    uint4 t = {cvt_tf32(v.x), cvt_tf32(v.y), cvt_tf32(v.z), cvt_tf32(v.w)};
    *(uint4*)(g_xtf + i) = t;
}
__global__ void cvt_w_kernel(const float* __restrict__ w) {
    const size_t i = ((size_t)blockIdx.x * 256 + threadIdx.x) * 4;
    float4 v = *(const float4*)(w + i);
    uint4 t = {cvt_tf32(v.x), cvt_tf32(v.y), cvt_tf32(v.z), cvt_tf32(v.w)};
    *(uint4*)(g_wtf + i) = t;
}

// ---------------------------------------------------------------------------
// Kernel 1 v2: x_pw = bn(W @ x) + x. tf32 mma.sync, cp.async 3-stage pipeline.
// CTA: M=128 x N=112, K=384, BK=16. Zero cvt in the hot loop (pre-converted).
// A smem [m][k] stride 20 (banks 20g+tig -> all 32 distinct);
// B smem [k][n] stride 120 (proven conflict-free fragment loads).
// ---------------------------------------------------------------------------
#define AW 20
#define BW 120
#define AWORDS (128 * AW)          // 2560
#define BWORDS (16 * BW)           // 1920
#define STW    (AWORDS + BWORDS)   // 4480 words per stage
#define GSMEM  (3 * STW * 4)       // 53760 B

__global__ void __launch_bounds__(256) gemm_pw_kernel(
    const float* __restrict__ x,
    const float* __restrict__ gg, const float* __restrict__ bb,
    const float* __restrict__ mm, const float* __restrict__ vv)
{
    extern __shared__ uint32_t gs[];

    const int tid = threadIdx.x;
    const int wid = tid >> 5;
    const int lane = tid & 31;
    const int g   = lane >> 2;
    const int tig = lane & 3;
    const int wm  = (wid & 3) * 32;
    const int wn  = (wid >> 2) * 56;

    const int bi = blockIdx.z;
    const int m0 = blockIdx.y * 128;
    const int p0 = blockIdx.x * 112;

    const uint32_t sbase = smem_u32(gs);
    const uint32_t* xtb = g_xtf + (size_t)bi * C_ * HWSZ + p0;

    // staging thread roles (constant across chunks)
    const int am0 = tid >> 2,       akq0 = tid & 3;           // A chunk 0
    const int am1 = (tid + 256) >> 2, akq1 = tid & 3;         // A chunk 1 (tid+256: kq same)
    const int bkr0 = tid / 28,      bhq0 = tid - bkr0 * 28;   // B chunk 0 (tid<256 all? 448 total)
    const int bq1 = tid + 256;
    const int bkr1 = bq1 / 28,      bhq1 = bq1 - bkr1 * 28;
    const bool bv1 = bq1 < 448;

    float acc[2][7][4];
#pragma unroll
    for (int mt = 0; mt < 2; mt++)
#pragma unroll
        for (int nt = 0; nt < 7; nt++)
#pragma unroll
            for (int q = 0; q < 4; q++) acc[mt][nt][q] = 0.f;

    // issue cp.async for chunk kc into stage s
    auto stage_chunk = [&](int kc, int s) {
        const uint32_t aB = sbase + (s * STW) * 4;
        const uint32_t bB = aB + AWORDS * 4;
        // A: 512 x 16B
        CP_ASYNC16(aB + (am0 * AW + akq0 * 4) * 4,
                   g_wtf + (size_t)(m0 + am0) * C_ + kc * 16 + akq0 * 4);
        CP_ASYNC16(aB + (am1 * AW + akq1 * 4) * 4,
                   g_wtf + (size_t)(m0 + am1) * C_ + kc * 16 + akq1 * 4);
        // B: 448 x 16B
        CP_ASYNC16(bB + (bkr0 * BW + bhq0 * 4) * 4,
                   xtb + (size_t)(kc * 16 + bkr0) * HWSZ + bhq0 * 4);
        if (bv1)
            CP_ASYNC16(bB + (bkr1 * BW + bhq1 * 4) * 4,
                       xtb + (size_t)(kc * 16 + bkr1) * HWSZ + bhq1 * 4);
    };

    // prologue: chunks 0,1 -> groups 0,1
    stage_chunk(0, 0); CP_COMMIT();
    stage_chunk(1, 1); CP_COMMIT();

    for (int kc = 0; kc < 24; kc++) {
        CP_WAIT1();              // group kc complete (<=1 newer pending)
        __syncthreads();
        if (kc + 2 < 24) stage_chunk(kc + 2, (kc + 2) % 3);
        CP_COMMIT();             // always commit to keep group numbering aligned

        const uint32_t* As = gs + (kc % 3) * STW;
        const uint32_t* Bs = As + AWORDS;
#pragma unroll
        for (int kk = 0; kk < 2; kk++) {
            const int kcol = kk * 8 + tig;
            uint32_t a[2][4], b[7][2];
#pragma unroll
            for (int mt = 0; mt < 2; mt++) {
                const uint32_t* ap = As + (wm + mt * 16 + g) * AW + kcol;
                a[mt][0] = ap[0];
                a[mt][1] = ap[8 * AW];
                a[mt][2] = ap[4];
                a[mt][3] = ap[8 * AW + 4];
            }
            const uint32_t* bp0 = Bs + kcol * BW + wn + g;
            const uint32_t* bp4 = bp0 + 4 * BW;
#pragma unroll
            for (int nt = 0; nt < 7; nt++) {
                b[nt][0] = bp0[nt * 8];
                b[nt][1] = bp4[nt * 8];
            }
#pragma unroll
            for (int mt = 0; mt < 2; mt++)
#pragma unroll
                for (int nt = 0; nt < 7; nt++)
                    MMA_TF32(acc[mt][nt], a[mt], b[nt]);
        }
        __syncthreads();
    }

    // ---- epilogue: BN + residual -> g_xpw ----
    float sc[2][2], sh[2][2];
#pragma unroll
    for (int mt = 0; mt < 2; mt++)
#pragma unroll
        for (int h = 0; h < 2; h++) {
            const int o = m0 + wm + mt * 16 + h * 8 + g;
            const float s = gg[o] * rsqrtf(vv[o] + EPSV);
            sc[mt][h] = s;
            sh[mt][h] = fmaf(-mm[o], s, bb[o]);
        }

#pragma unroll
    for (int mt = 0; mt < 2; mt++)
#pragma unroll
        for (int h = 0; h < 2; h++) {
            const int o = m0 + wm + mt * 16 + h * 8 + g;
            const size_t rb = ((size_t)bi * C_ + o) * HWSZ + p0 + wn + 2 * tig;
#pragma unroll
            for (int nt = 0; nt < 7; nt++) {
                const size_t idx = rb + nt * 8;
                float2 xr = *(const float2*)(x + idx);
                const float c0 = acc[mt][nt][h * 2 + 0];
                const float c1 = acc[mt][nt][h * 2 + 1];
                float2 ov;
                ov.x = fmaf(c0, sc[mt][h], sh[mt][h]) + xr.x;
                ov.y = fmaf(c1, sc[mt][h], sh[mt][h]) + xr.y;
                *(float2*)(g_xpw + idx) = ov;
            }
        }
}

// ---------------------------------------------------------------------------
// Kernel 2 (round-1 proven, 236us): out = gelu(bn(dwconv13(x_pw)) + bn(x_pw*dw1_w))
// ---------------------------------------------------------------------------
__global__ void __launch_bounds__(224) dw_bn_gelu_kernel(
    const float* __restrict__ kw,
    const float* __restrict__ kg,  const float* __restrict__ kb,
    const float* __restrict__ km,  const float* __restrict__ kv,
    const float* __restrict__ d1w, const float* __restrict__ d1g,
    const float* __restrict__ d1b, const float* __restrict__ d1m,
    const float* __restrict__ d1v,
    float* __restrict__ out)
{
    __shared__ float s_in[28 * 72];
    __shared__ float s_w[169];

    const int band = blockIdx.x;
    const int c    = blockIdx.y;
    const int bi   = blockIdx.z;
    const int tid  = threadIdx.x;
    const int r0   = band * 16;

    const float* src = g_xpw + ((size_t)bi * C_ + c) * HWSZ;

    for (int idx = tid; idx < 28 * 68; idx += 224) {
        const int row = idx / 68;
        const int col = idx - row * 68;
        const int gh = r0 - 6 + row;
        const int gw = col - 6;
        float val = 0.f;
        if (gh >= 0 && gh < HH && gw >= 0 && gw < WW) val = src[gh * WW + gw];
        s_in[row * 72 + col] = val;
    }
    if (tid < 169) s_w[tid] = kw[(size_t)c * 169 + tid];
    __syncthreads();

    const int tx = tid % 14;
    const int ty = tid / 14;
    const int orow = r0 + ty;
    if (orow >= HH) return;

    const int x4 = tx * 4;
    float acc0 = 0.f, acc1 = 0.f, acc2 = 0.f, acc3 = 0.f;

#pragma unroll
    for (int i = 0; i < 13; i++) {
        const float* rp = s_in + (ty + i) * 72 + x4;
        float r[16];
        *(float4*)&r[0]  = *(const float4*)(rp);
        *(float4*)&r[4]  = *(const float4*)(rp + 4);
        *(float4*)&r[8]  = *(const float4*)(rp + 8);
        *(float4*)&r[12] = *(const float4*)(rp + 12);
#pragma unroll
        for (int j = 0; j < 13; j++) {
            const float wv = s_w[i * 13 + j];
            acc0 = fmaf(r[j + 0], wv, acc0);
            acc1 = fmaf(r[j + 1], wv, acc1);
            acc2 = fmaf(r[j + 2], wv, acc2);
            acc3 = fmaf(r[j + 3], wv, acc3);
        }
    }

    const float sk  = kg[c] * rsqrtf(kv[c] + EPSV);
    const float shk = fmaf(-km[c], sk, kb[c]);
    const float s1  = d1g[c] * rsqrtf(d1v[c] + EPSV);
    const float a2  = d1w[c] * s1;
    const float b2  = fmaf(-d1m[c], s1, d1b[c]);

    const float* cp = s_in + (ty + 6) * 72 + x4 + 6;
    const float v0 = fmaf(acc0, sk, shk) + fmaf(cp[0], a2, b2);
    const float v1 = fmaf(acc1, sk, shk) + fmaf(cp[1], a2, b2);
    const float v2 = fmaf(acc2, sk, shk) + fmaf(cp[2], a2, b2);
    const float v3 = fmaf(acc3, sk, shk) + fmaf(cp[3], a2, b2);

    const float RS2 = 0.70710678118654752f;
    float4 res;
    res.x = 0.5f * v0 * (1.f + erff(v0 * RS2));
    res.y = 0.5f * v1 * (1.f + erff(v1 * RS2));
    res.z = 0.5f * v2 * (1.f + erff(v2 * RS2));
    res.w = 0.5f * v3 * (1.f + erff(v3 * RS2));

    *(float4*)(out + ((size_t)bi * C_ + c) * HWSZ + orow * WW + x4) = res;
}

// ---------------------------------------------------------------------------
extern "C" void kernel_launch(void* const* d_in, const int* in_sizes, int n_in,
                              void* d_out, int out_size)
{
    const float* x     = (const float*)d_in[0];
    const float* pw_w  = (const float*)d_in[1];
    const float* pw_g  = (const float*)d_in[2];
    const float* pw_b  = (const float*)d_in[3];
    const float* pw_m  = (const float*)d_in[4];
    const float* pw_v  = (const float*)d_in[5];
    const float* dwk_w = (const float*)d_in[6];
    const float* dwk_g = (const float*)d_in[7];
    const float* dwk_b = (const float*)d_in[8];
    const float* dwk_m = (const float*)d_in[9];
    const float* dwk_v = (const float*)d_in[10];
    const float* dw1_w = (const float*)d_in[11];
    const float* dw1_g = (const float*)d_in[12];
    const float* dw1_b = (const float*)d_in[13];
    const float* dw1_m = (const float*)d_in[14];
    const float* dw1_v = (const float*)d_in[15];
    float* out = (float*)d_out;

    // Pre-convert X and W to tf32 (rna)
    cvt_x_kernel<<<(NB * C_ * HWSZ) / 1024, 256>>>(x);          // 18816 blocks
    cvt_w_kernel<<<(C_ * C_) / 1024, 256>>>(pw_w);              // 144 blocks

    cudaFuncSetAttribute(gemm_pw_kernel,
                         cudaFuncAttributeMaxDynamicSharedMemorySize, GSMEM);
    dim3 g1(HWSZ / 112, C_ / 128, NB);   // (28, 3, 16)
    gemm_pw_kernel<<<g1, 256, GSMEM>>>(x, pw_g, pw_b, pw_m, pw_v);

    dim3 g2((HH + 15) / 16, C_, NB);     // (4, 384, 16)
    dw_bn_gelu_kernel<<<g2, 224>>>(dwk_w, dwk_g, dwk_b, dwk_m, dwk_v,
                                   dw1_w, dw1_g, dw1_b, dw1_m, dw1_v, out);
}